// round 9
// baseline (speedup 1.0000x reference)
#include <cuda_runtime.h>
#include <cstdint>

typedef unsigned long long u64;

#define DT_F      0.1f
#define NITERS    9               // int(1.0 // 0.1) == 9 in Python float semantics!
#define BATCH     64
#define NN        1024
#define NOBS      64
#define NACT      16
#define CPB       16              // CTAs per batch (= cluster size)
#define ROWS_CTA  64              // rows per CTA (32 in regs + 32 in smem)
#define NCLUST    8               // clusters (groups)
#define BPG       (BATCH / NCLUST)   // 8 batches per cluster
#define NTHREADS  256

// ===================== shared helpers =====================
__device__ __forceinline__ void mbar_init(uint32_t a, uint32_t cnt) {
    asm volatile("mbarrier.init.shared.b64 [%0], %1;" :: "r"(a), "r"(cnt) : "memory");
}
__device__ __forceinline__ void mbar_expect_tx(uint32_t a, uint32_t bytes) {
    asm volatile("mbarrier.arrive.expect_tx.shared.b64 _, [%0], %1;" :: "r"(a), "r"(bytes) : "memory");
}
__device__ __forceinline__ void mbar_wait(uint32_t a, uint32_t parity) {
    asm volatile(
        "{\n\t.reg .pred P;\n\t"
        "W_%=:\n\t"
        "mbarrier.try_wait.parity.shared.b64 P, [%0], %1;\n\t"
        "@P bra.uni D_%=;\n\t"
        "bra.uni W_%=;\n\t"
        "D_%=:\n\t}"
        :: "r"(a), "r"(parity) : "memory");
}
__device__ __forceinline__ void bulk_g2s(uint32_t dst, const void* src, uint32_t bytes, uint32_t mbar) {
    asm volatile(
        "cp.async.bulk.shared::cta.global.mbarrier::complete_tx::bytes [%0], [%1], %2, [%3];"
        :: "r"(dst), "l"(src), "r"(bytes), "r"(mbar) : "memory");
}
__device__ __forceinline__ void issue_chunks(uint32_t dst, const char* gsrc,
                                             uint32_t bytes, uint32_t mbar) {
    asm volatile("fence.proxy.async.shared::cta;" ::: "memory");
    mbar_expect_tx(mbar, bytes);
    for (uint32_t c = 0; c < bytes; c += 32768)
        bulk_g2s(dst + c, gsrc + c, 32768, mbar);
}

// ===================== cluster-path helpers =====================
__device__ __forceinline__ uint32_t mapa_u32(uint32_t a, uint32_t rank) {
    uint32_t r;
    asm volatile("mapa.shared::cluster.u32 %0, %1, %2;" : "=r"(r) : "r"(a), "r"(rank));
    return r;
}
__device__ __forceinline__ void st_cluster_f32(uint32_t a, float v) {
    asm volatile("st.shared::cluster.f32 [%0], %1;" :: "r"(a), "f"(v) : "memory");
}
__device__ __forceinline__ void arrive_cluster(uint32_t a) {
    asm volatile("mbarrier.arrive.release.cluster.shared::cluster.b64 _, [%0];"
                 :: "r"(a) : "memory");
}
__device__ __forceinline__ void ybar_wait(uint32_t a, uint32_t parity) {
    asm volatile(
        "{\n\t.reg .pred P;\n\t"
        "W_%=:\n\t"
        "mbarrier.try_wait.parity.acquire.cluster.shared::cta.b64 P, [%0], %1, 0x989680;\n\t"
        "@P bra.uni D_%=;\n\t"
        "bra.uni W_%=;\n\t"
        "D_%=:\n\t}"
        :: "r"(a), "r"(parity) : "memory");
}

// ===================== cluster kernel SMEM layout =====================
#define S1_OFF    0               // smem W half (32 rows)          131072 B
#define S0_OFF    131072          // staging (16 rows)               65536 B
#define YB_OFF    196608          // ybuf[2][1024] floats             8192 B
#define P_OFF     204800          // P[6][64]                         1536 B
#define OBS_OFF   206336          // obs_s[64]                         256 B
#define RED_OFF   206592          // red_s[8]                           32 B
#define BAR_OFF   206624          // wbar0,wbar1,ybar0,ybar1            32 B
#define SMEM_BYTES 206656

__global__ __launch_bounds__(NTHREADS, 1)
void ctrnn_cluster_kernel(const float* __restrict__ obs,  const float* __restrict__ v0,
                          const float* __restrict__ tau,  const float* __restrict__ gain,
                          const float* __restrict__ bias, const float* __restrict__ W,
                          const float* __restrict__ mask, const float* __restrict__ E,
                          const float* __restrict__ D,    float* __restrict__ out)
{
    extern __shared__ char sm[];
    float4* S1f4  = (float4*)(sm + S1_OFF);
    float4* S0f4  = (float4*)(sm + S0_OFF);
    float*  YB    = (float*)(sm + YB_OFF);     // [2][1024] plain floats
    float*  P     = (float*)(sm + P_OFF);      // [6][64]
    float*  obs_s = (float*)(sm + OBS_OFF);
    float*  red_s = (float*)(sm + RED_OFF);

    const int tid  = threadIdx.x;
    const int warp = tid >> 5;
    const int lane = tid & 31;
    const int group = blockIdx.x >> 4;
    const int cig   = blockIdx.x & 15;         // == cluster ctarank
    const int base  = cig * ROWS_CTA;

    const uint32_t S0a   = (uint32_t)__cvta_generic_to_shared(S0f4);
    const uint32_t S1a   = (uint32_t)__cvta_generic_to_shared(S1f4);
    const uint32_t YBa   = (uint32_t)__cvta_generic_to_shared(YB);
    const uint32_t wbar0 = (uint32_t)__cvta_generic_to_shared(sm + BAR_OFF);
    const uint32_t wbar1 = wbar0 + 8;
    const uint32_t ybar0 = wbar0 + 16;
    const uint32_t ybar1 = wbar0 + 24;

    if (tid == 0) {
        mbar_init(wbar0, 1);
        mbar_init(wbar1, 1);
        mbar_init(ybar0, 16);   // 16 producer-CTA arrivals per phase
        mbar_init(ybar1, 16);
        asm volatile("fence.proxy.async.shared::cta;" ::: "memory");
    }
    __syncthreads();
    // all CTAs' ybar inits must be visible before any remote arrive
    asm volatile("barrier.cluster.arrive.aligned;" ::: "memory");
    asm volatile("barrier.cluster.wait.aligned;"   ::: "memory");

    if (tid == 0) {
        const char* g = (const char*)(W + ((size_t)(group * BPG) * NN + base) * NN);
        issue_chunks(S0a, g, 65536, wbar0);      // part1 of batch 0
    }

    float4 Wreg[4][8];
    int cw0 = 0, cw1 = 0;       // W-load mbar phases
    int cy0 = 0, cy1 = 0;       // y-exchange mbar phases

    for (int bi = 0; bi < BPG; bi++) {
        const int b = group * BPG + bi;
        const char* gW = (const char*)(W + ((size_t)b * NN + base) * NN);

        // ---------- W: part1 -> registers (warps 0-3) ----------
        mbar_wait(wbar0, (uint32_t)(cw0 & 1)); cw0++;
        if (warp < 4) {
            #pragma unroll
            for (int r = 0; r < 4; r++)
                #pragma unroll
                for (int j = 0; j < 8; j++)
                    Wreg[r][j] = S0f4[(warp * 4 + r) * 256 + j * 32 + lane];
        }
        __syncthreads();
        if (tid == 0) {
            issue_chunks(S0a, gW + 65536, 65536, wbar0);     // part2
            issue_chunks(S1a, gW + 131072, 131072, wbar1);   // smem half
        }

        // ---------- prologue: params + y0 push to all 16 CTAs ----------
        if (tid < NOBS) obs_s[tid] = obs[(size_t)b * NOBS + tid];
        __syncthreads();
        if (tid < ROWS_CTA) {
            const int n = base + tid;
            const size_t o = (size_t)b * NN + n;
            float vv = v0[o], gg = gain[o], bb = bias[o], mm = mask[o];
            P[0 * 64 + tid] = vv;
            P[1 * 64 + tid] = DT_F / tau[o];
            P[3 * 64 + tid] = gg;
            P[4 * 64 + tid] = bb;
            P[5 * 64 + tid] = mm;
            const float* Er = E + o * NOBS;
            float s = 0.f;
            #pragma unroll
            for (int q = 0; q < NOBS; q++) s += Er[q] * obs_s[q];
            P[2 * 64 + tid] = s;
            float y0 = tanhf(gg * (vv + bb)) * mm;
            const uint32_t la = YBa + (uint32_t)(0 * NN + n) * 4u;   // ybuf[0][n]
            #pragma unroll
            for (int k = 0; k < CPB; k++)
                st_cluster_f32(mapa_u32(la, (uint32_t)k), y0);
        }
        __syncthreads();                                   // all y0 stores issued
        if (warp == 0 && lane < CPB)
            arrive_cluster(mapa_u32(ybar0, (uint32_t)lane));

        // ---------- W: part2 -> registers (warps 4-7); smem half ready ----------
        mbar_wait(wbar0, (uint32_t)(cw0 & 1)); cw0++;
        if (warp >= 4) {
            #pragma unroll
            for (int r = 0; r < 4; r++)
                #pragma unroll
                for (int j = 0; j < 8; j++)
                    Wreg[r][j] = S0f4[((warp - 4) * 4 + r) * 256 + j * 32 + lane];
        }
        mbar_wait(wbar1, (uint32_t)(cw1 & 1)); cw1++;
        __syncthreads();                                   // S0 free
        if (tid == 0 && bi + 1 < BPG) {
            const char* gn = (const char*)(W + ((size_t)(b + 1) * NN + base) * NN);
            issue_chunks(S0a, gn, 65536, wbar0);           // next part1
        }

        // ---------- iterations ----------
        const float4* S1w = S1f4 + (size_t)(warp * 4) * 256;
        for (int t = 1; t <= NITERS; t++) {
            // wait for step t-1 data (parity (t-1)&1) in LOCAL ybuf
            if (((t - 1) & 1) == 0) { ybar_wait(ybar0, (uint32_t)(cy0 & 1)); cy0++; }
            else                     { ybar_wait(ybar1, (uint32_t)(cy1 & 1)); cy1++; }
            const float4* Y4 = (const float4*)(YB + ((t - 1) & 1) * NN);

            float ar0 = 0.f, ar1 = 0.f, ar2 = 0.f, ar3 = 0.f;
            float as0 = 0.f, as1 = 0.f, as2 = 0.f, as3 = 0.f;
            #pragma unroll
            for (int j = 0; j < 8; j++) {
                const float4 y4 = Y4[j * 32 + lane];
                float4 w;
                w = Wreg[0][j];                   ar0 += w.x*y4.x; ar0 += w.y*y4.y; ar0 += w.z*y4.z; ar0 += w.w*y4.w;
                w = Wreg[1][j];                   ar1 += w.x*y4.x; ar1 += w.y*y4.y; ar1 += w.z*y4.z; ar1 += w.w*y4.w;
                w = Wreg[2][j];                   ar2 += w.x*y4.x; ar2 += w.y*y4.y; ar2 += w.z*y4.z; ar2 += w.w*y4.w;
                w = Wreg[3][j];                   ar3 += w.x*y4.x; ar3 += w.y*y4.y; ar3 += w.z*y4.z; ar3 += w.w*y4.w;
                w = S1w[0 * 256 + j * 32 + lane]; as0 += w.x*y4.x; as0 += w.y*y4.y; as0 += w.z*y4.z; as0 += w.w*y4.w;
                w = S1w[1 * 256 + j * 32 + lane]; as1 += w.x*y4.x; as1 += w.y*y4.y; as1 += w.z*y4.z; as1 += w.w*y4.w;
                w = S1w[2 * 256 + j * 32 + lane]; as2 += w.x*y4.x; as2 += w.y*y4.y; as2 += w.z*y4.z; as2 += w.w*y4.w;
                w = S1w[3 * 256 + j * 32 + lane]; as3 += w.x*y4.x; as3 += w.y*y4.y; as3 += w.z*y4.z; as3 += w.w*y4.w;
            }
            #pragma unroll
            for (int off = 16; off > 0; off >>= 1) {
                ar0 += __shfl_xor_sync(0xffffffffu, ar0, off);
                ar1 += __shfl_xor_sync(0xffffffffu, ar1, off);
                ar2 += __shfl_xor_sync(0xffffffffu, ar2, off);
                ar3 += __shfl_xor_sync(0xffffffffu, ar3, off);
                as0 += __shfl_xor_sync(0xffffffffu, as0, off);
                as1 += __shfl_xor_sync(0xffffffffu, as1, off);
                as2 += __shfl_xor_sync(0xffffffffu, as2, off);
                as3 += __shfl_xor_sync(0xffffffffu, as3, off);
            }

            if (lane < 8) {
                float dot;
                int rloc;
                if (lane < 4) {
                    dot  = (lane == 0) ? ar0 : (lane == 1) ? ar1 : (lane == 2) ? ar2 : ar3;
                    rloc = warp * 4 + lane;
                } else {
                    dot  = (lane == 4) ? as0 : (lane == 5) ? as1 : (lane == 6) ? as2 : as3;
                    rloc = 32 + warp * 4 + (lane - 4);
                }
                float v  = P[0 * 64 + rloc];
                float nv = (v + P[1 * 64 + rloc] * (dot + P[2 * 64 + rloc] - v)) * P[5 * 64 + rloc];
                P[0 * 64 + rloc] = nv;
                float ov = (t < NITERS)
                    ? tanhf(P[3 * 64 + rloc] * (nv + P[4 * 64 + rloc])) * P[5 * 64 + rloc]
                    : nv;
                const uint32_t la = YBa + (uint32_t)((t & 1) * NN + base + rloc) * 4u;
                #pragma unroll
                for (int k = 0; k < CPB; k++)
                    st_cluster_f32(mapa_u32(la, (uint32_t)k), ov);
            }
            __syncthreads();                               // all stores issued
            if (warp == 0 && lane < CPB)
                arrive_cluster(mapa_u32((t & 1) ? ybar1 : ybar0, (uint32_t)lane));
        }

        // ---------- decode: wait final v (t=9, parity 1), each CTA one action ----------
        ybar_wait(ybar1, (uint32_t)(cy1 & 1)); cy1++;
        {
            const float* vf = YB + NN;                     // ybuf[1] holds final v
            const float* Dr = D + ((size_t)b * NACT + cig) * NN;
            float p = 0.f;
            for (int i = tid; i < NN; i += NTHREADS) p += Dr[i] * vf[i];
            #pragma unroll
            for (int off = 16; off > 0; off >>= 1)
                p += __shfl_xor_sync(0xffffffffu, p, off);
            if (lane == 0) red_s[warp] = p;
            __syncthreads();
            if (tid == 0) {
                float s = 0.f;
                #pragma unroll
                for (int j = 0; j < 8; j++) s += red_s[j];
                out[b * NACT + cig] = s;
            }
        }
        __syncthreads();                                   // P/red/obs free for next batch
    }
}

// ===================== fallback: R8 L2 tag-exchange kernel =====================
__device__ u64 g_ybuf[2][BATCH][NN];

__global__ void ctrnn_init_kernel() {
    int i = blockIdx.x * blockDim.x + threadIdx.x;
    if (i < 2 * BATCH * NN) ((u64*)g_ybuf)[i] = 0ull;
}
__device__ __forceinline__ u64 ldcg64(const u64* p) {
    u64 v;
    asm volatile("ld.global.cg.u64 %0, [%1];" : "=l"(v) : "l"(p));
    return v;
}
__device__ __forceinline__ void stcg64(u64* p, u64 v) {
    asm volatile("st.global.cg.u64 [%0], %1;" :: "l"(p), "l"(v) : "memory");
}
__device__ __forceinline__ void settle4(const u64* src, unsigned exp, float* y_s, int tid) {
    u64 r0 = ldcg64(src + tid);
    u64 r1 = ldcg64(src + tid + 256);
    u64 r2 = ldcg64(src + tid + 512);
    u64 r3 = ldcg64(src + tid + 768);
    while ((unsigned)(r0 >> 32) != exp) { __nanosleep(20); r0 = ldcg64(src + tid); }
    while ((unsigned)(r1 >> 32) != exp) { __nanosleep(20); r1 = ldcg64(src + tid + 256); }
    while ((unsigned)(r2 >> 32) != exp) { __nanosleep(20); r2 = ldcg64(src + tid + 512); }
    while ((unsigned)(r3 >> 32) != exp) { __nanosleep(20); r3 = ldcg64(src + tid + 768); }
    y_s[tid]       = __uint_as_float((unsigned)(r0 & 0xffffffffu));
    y_s[tid + 256] = __uint_as_float((unsigned)(r1 & 0xffffffffu));
    y_s[tid + 512] = __uint_as_float((unsigned)(r2 & 0xffffffffu));
    y_s[tid + 768] = __uint_as_float((unsigned)(r3 & 0xffffffffu));
}

#define FB_YS_OFF  196608
#define FB_P_OFF   204800
#define FB_OBS_OFF 206336
#define FB_RED_OFF 206592
#define FB_MB_OFF  206624

__global__ __launch_bounds__(NTHREADS, 1)
void ctrnn_l2_kernel(const float* __restrict__ obs,  const float* __restrict__ v0,
                     const float* __restrict__ tau,  const float* __restrict__ gain,
                     const float* __restrict__ bias, const float* __restrict__ W,
                     const float* __restrict__ mask, const float* __restrict__ E,
                     const float* __restrict__ D,    float* __restrict__ out)
{
    extern __shared__ char sm[];
    float4* S1f4  = (float4*)(sm + S1_OFF);
    float4* S0f4  = (float4*)(sm + S0_OFF);
    float*  y_s0  = (float*)(sm + FB_YS_OFF);
    float*  y_s1  = y_s0 + NN;
    float*  P     = (float*)(sm + FB_P_OFF);
    float*  obs_s = (float*)(sm + FB_OBS_OFF);
    float*  red_s = (float*)(sm + FB_RED_OFF);

    const int tid  = threadIdx.x;
    const int warp = tid >> 5;
    const int lane = tid & 31;
    const int group = blockIdx.x >> 4;
    const int cig   = blockIdx.x & 15;
    const int base  = cig * ROWS_CTA;

    const uint32_t mbar0 = (uint32_t)__cvta_generic_to_shared(sm + FB_MB_OFF);
    const uint32_t mbar1 = mbar0 + 8;
    const uint32_t S0a   = (uint32_t)__cvta_generic_to_shared(S0f4);
    const uint32_t S1a   = (uint32_t)__cvta_generic_to_shared(S1f4);

    if (tid == 0) {
        mbar_init(mbar0, 1);
        mbar_init(mbar1, 1);
        asm volatile("fence.proxy.async.shared::cta;" ::: "memory");
    }
    __syncthreads();
    if (tid == 0) {
        const char* g = (const char*)(W + ((size_t)(group * BPG) * NN + base) * NN);
        issue_chunks(S0a, g, 65536, mbar0);
    }

    float4 Wreg[4][8];
    int li0 = 0, li1 = 0;

    for (int bi = 0; bi < BPG; bi++) {
        const int b = group * BPG + bi;
        const char* gW = (const char*)(W + ((size_t)b * NN + base) * NN);

        mbar_wait(mbar0, (uint32_t)(li0 & 1)); li0++;
        if (warp < 4) {
            #pragma unroll
            for (int r = 0; r < 4; r++)
                #pragma unroll
                for (int j = 0; j < 8; j++)
                    Wreg[r][j] = S0f4[(warp * 4 + r) * 256 + j * 32 + lane];
        }
        __syncthreads();
        if (tid == 0) {
            issue_chunks(S0a, gW + 65536, 65536, mbar0);
            issue_chunks(S1a, gW + 131072, 131072, mbar1);
        }

        if (tid < NOBS) obs_s[tid] = obs[(size_t)b * NOBS + tid];
        __syncthreads();
        if (tid < ROWS_CTA) {
            const int n = base + tid;
            const size_t o = (size_t)b * NN + n;
            float vv = v0[o], gg = gain[o], bb = bias[o], mm = mask[o];
            P[0 * 64 + tid] = vv;
            P[1 * 64 + tid] = DT_F / tau[o];
            P[3 * 64 + tid] = gg;
            P[4 * 64 + tid] = bb;
            P[5 * 64 + tid] = mm;
            const float* Er = E + o * NOBS;
            float s = 0.f;
            #pragma unroll
            for (int q = 0; q < NOBS; q++) s += Er[q] * obs_s[q];
            P[2 * 64 + tid] = s;
            float y0 = tanhf(gg * (vv + bb)) * mm;
            stcg64(&g_ybuf[0][b][n], ((u64)1 << 32) | (u64)__float_as_uint(y0));
        }

        mbar_wait(mbar0, (uint32_t)(li0 & 1)); li0++;
        if (warp >= 4) {
            #pragma unroll
            for (int r = 0; r < 4; r++)
                #pragma unroll
                for (int j = 0; j < 8; j++)
                    Wreg[r][j] = S0f4[((warp - 4) * 4 + r) * 256 + j * 32 + lane];
        }
        mbar_wait(mbar1, (uint32_t)(li1 & 1)); li1++;
        __syncthreads();
        if (tid == 0 && bi + 1 < BPG) {
            const char* gn = (const char*)(W + ((size_t)(b + 1) * NN + base) * NN);
            issue_chunks(S0a, gn, 65536, mbar0);
        }

        const float4* S1w = S1f4 + (size_t)(warp * 4) * 256;
        for (int t = 1; t <= NITERS; t++) {
            float* ys = (t & 1) ? y_s1 : y_s0;
            settle4(&g_ybuf[(t - 1) & 1][b][0], (unsigned)t, ys, tid);
            __syncthreads();
            const float4* Y4 = (const float4*)ys;

            float ar0 = 0.f, ar1 = 0.f, ar2 = 0.f, ar3 = 0.f;
            float as0 = 0.f, as1 = 0.f, as2 = 0.f, as3 = 0.f;
            #pragma unroll
            for (int j = 0; j < 8; j++) {
                const float4 y4 = Y4[j * 32 + lane];
                float4 w;
                w = Wreg[0][j];                   ar0 += w.x*y4.x; ar0 += w.y*y4.y; ar0 += w.z*y4.z; ar0 += w.w*y4.w;
                w = Wreg[1][j];                   ar1 += w.x*y4.x; ar1 += w.y*y4.y; ar1 += w.z*y4.z; ar1 += w.w*y4.w;
                w = Wreg[2][j];                   ar2 += w.x*y4.x; ar2 += w.y*y4.y; ar2 += w.z*y4.z; ar2 += w.w*y4.w;
                w = Wreg[3][j];                   ar3 += w.x*y4.x; ar3 += w.y*y4.y; ar3 += w.z*y4.z; ar3 += w.w*y4.w;
                w = S1w[0 * 256 + j * 32 + lane]; as0 += w.x*y4.x; as0 += w.y*y4.y; as0 += w.z*y4.z; as0 += w.w*y4.w;
                w = S1w[1 * 256 + j * 32 + lane]; as1 += w.x*y4.x; as1 += w.y*y4.y; as1 += w.z*y4.z; as1 += w.w*y4.w;
                w = S1w[2 * 256 + j * 32 + lane]; as2 += w.x*y4.x; as2 += w.y*y4.y; as2 += w.z*y4.z; as2 += w.w*y4.w;
                w = S1w[3 * 256 + j * 32 + lane]; as3 += w.x*y4.x; as3 += w.y*y4.y; as3 += w.z*y4.z; as3 += w.w*y4.w;
            }
            #pragma unroll
            for (int off = 16; off > 0; off >>= 1) {
                ar0 += __shfl_xor_sync(0xffffffffu, ar0, off);
                ar1 += __shfl_xor_sync(0xffffffffu, ar1, off);
                ar2 += __shfl_xor_sync(0xffffffffu, ar2, off);
                ar3 += __shfl_xor_sync(0xffffffffu, ar3, off);
                as0 += __shfl_xor_sync(0xffffffffu, as0, off);
                as1 += __shfl_xor_sync(0xffffffffu, as1, off);
                as2 += __shfl_xor_sync(0xffffffffu, as2, off);
                as3 += __shfl_xor_sync(0xffffffffu, as3, off);
            }
            if (lane < 8) {
                float dot;
                int rloc;
                if (lane < 4) {
                    dot  = (lane == 0) ? ar0 : (lane == 1) ? ar1 : (lane == 2) ? ar2 : ar3;
                    rloc = warp * 4 + lane;
                } else {
                    dot  = (lane == 4) ? as0 : (lane == 5) ? as1 : (lane == 6) ? as2 : as3;
                    rloc = 32 + warp * 4 + (lane - 4);
                }
                float v  = P[0 * 64 + rloc];
                float nv = (v + P[1 * 64 + rloc] * (dot + P[2 * 64 + rloc] - v)) * P[5 * 64 + rloc];
                P[0 * 64 + rloc] = nv;
                float ov = (t < NITERS)
                    ? tanhf(P[3 * 64 + rloc] * (nv + P[4 * 64 + rloc])) * P[5 * 64 + rloc]
                    : nv;
                stcg64(&g_ybuf[t & 1][b][base + rloc],
                       ((u64)(unsigned)(t + 1) << 32) | (u64)__float_as_uint(ov));
            }
        }

        settle4(&g_ybuf[NITERS & 1][b][0], (unsigned)(NITERS + 1), y_s0, tid);
        __syncthreads();
        {
            const float* Dr = D + ((size_t)b * NACT + cig) * NN;
            float p = 0.f;
            for (int i = tid; i < NN; i += NTHREADS) p += Dr[i] * y_s0[i];
            #pragma unroll
            for (int off = 16; off > 0; off >>= 1)
                p += __shfl_xor_sync(0xffffffffu, p, off);
            if (lane == 0) red_s[warp] = p;
            __syncthreads();
            if (tid == 0) {
                float s = 0.f;
                #pragma unroll
                for (int j = 0; j < 8; j++) s += red_s[j];
                out[b * NACT + cig] = s;
            }
        }
        __syncthreads();
    }
}

// ===================== launcher =====================
extern "C" void kernel_launch(void* const* d_in, const int* in_sizes, int n_in,
                              void* d_out, int out_size) {
    const float* obs  = (const float*)d_in[0];
    const float* v0   = (const float*)d_in[1];
    const float* tau  = (const float*)d_in[2];
    const float* gain = (const float*)d_in[3];
    const float* bias = (const float*)d_in[4];
    const float* W    = (const float*)d_in[5];
    const float* mask = (const float*)d_in[6];
    const float* E    = (const float*)d_in[7];
    const float* D    = (const float*)d_in[8];
    float* out = (float*)d_out;

    cudaFuncSetAttribute(ctrnn_cluster_kernel,
                         cudaFuncAttributeMaxDynamicSharedMemorySize, SMEM_BYTES);
    cudaFuncSetAttribute(ctrnn_cluster_kernel,
                         cudaFuncAttributeNonPortableClusterSizeAllowed, 1);

    cudaLaunchConfig_t cfg = {};
    cfg.gridDim  = dim3(NCLUST * CPB, 1, 1);
    cfg.blockDim = dim3(NTHREADS, 1, 1);
    cfg.dynamicSmemBytes = SMEM_BYTES;
    cudaLaunchAttribute attrs[1];
    attrs[0].id = cudaLaunchAttributeClusterDimension;
    attrs[0].val.clusterDim.x = CPB;
    attrs[0].val.clusterDim.y = 1;
    attrs[0].val.clusterDim.z = 1;
    cfg.attrs = attrs;
    cfg.numAttrs = 1;

    int maxClusters = 0;
    cudaError_t qerr = cudaOccupancyMaxActiveClusters(&maxClusters,
                                                      ctrnn_cluster_kernel, &cfg);

    if (qerr == cudaSuccess && maxClusters >= NCLUST) {
        cudaLaunchKernelEx(&cfg, ctrnn_cluster_kernel,
                           obs, v0, tau, gain, bias, W, mask, E, D, out);
    } else {
        // fallback: proven L2 tag-exchange path (R8)
        cudaGetLastError();   // clear any sticky error from the query
        cudaFuncSetAttribute(ctrnn_l2_kernel,
                             cudaFuncAttributeMaxDynamicSharedMemorySize, SMEM_BYTES);
        ctrnn_init_kernel<<<(2 * BATCH * NN + 255) / 256, 256>>>();
        ctrnn_l2_kernel<<<NCLUST * CPB, NTHREADS, SMEM_BYTES>>>(
            obs, v0, tau, gain, bias, W, mask, E, D, out);
    }
}

// round 10
// speedup vs baseline: 1.0018x; 1.0018x over previous
#include <cuda_runtime.h>
#include <cstdint>

typedef unsigned long long u64;

#define DT_F      0.1f
#define NITERS    9               // int(1.0 // 0.1) == 9 in Python float semantics!
#define BATCH     64
#define NN        1024
#define NOBS      64
#define NACT      16
#define CPB       16              // CTAs per batch (= cluster size)
#define ROWS_CTA  64              // rows per CTA (32 in regs + 32 in smem)
#define NCLUST    8               // clusters (groups)
#define BPG       (BATCH / NCLUST)   // 8 batches per cluster
#define NTHREADS  256

// ===================== shared helpers =====================
__device__ __forceinline__ void mbar_init(uint32_t a, uint32_t cnt) {
    asm volatile("mbarrier.init.shared.b64 [%0], %1;" :: "r"(a), "r"(cnt) : "memory");
}
__device__ __forceinline__ void mbar_expect_tx(uint32_t a, uint32_t bytes) {
    asm volatile("mbarrier.arrive.expect_tx.shared.b64 _, [%0], %1;" :: "r"(a), "r"(bytes) : "memory");
}
__device__ __forceinline__ void mbar_wait(uint32_t a, uint32_t parity) {
    asm volatile(
        "{\n\t.reg .pred P;\n\t"
        "W_%=:\n\t"
        "mbarrier.try_wait.parity.shared.b64 P, [%0], %1;\n\t"
        "@P bra.uni D_%=;\n\t"
        "bra.uni W_%=;\n\t"
        "D_%=:\n\t}"
        :: "r"(a), "r"(parity) : "memory");
}
__device__ __forceinline__ void bulk_g2s(uint32_t dst, const void* src, uint32_t bytes, uint32_t mbar) {
    asm volatile(
        "cp.async.bulk.shared::cta.global.mbarrier::complete_tx::bytes [%0], [%1], %2, [%3];"
        :: "r"(dst), "l"(src), "r"(bytes), "r"(mbar) : "memory");
}
__device__ __forceinline__ void issue_chunks(uint32_t dst, const char* gsrc,
                                             uint32_t bytes, uint32_t mbar) {
    asm volatile("fence.proxy.async.shared::cta;" ::: "memory");
    mbar_expect_tx(mbar, bytes);
    for (uint32_t c = 0; c < bytes; c += 32768)
        bulk_g2s(dst + c, gsrc + c, 32768, mbar);
}

// ===================== cluster-path helpers =====================
__device__ __forceinline__ uint32_t mapa_u32(uint32_t a, uint32_t rank) {
    uint32_t r;
    asm volatile("mapa.shared::cluster.u32 %0, %1, %2;" : "=r"(r) : "r"(a), "r"(rank));
    return r;
}
__device__ __forceinline__ void st_cluster_f32(uint32_t a, float v) {
    asm volatile("st.shared::cluster.f32 [%0], %1;" :: "r"(a), "f"(v) : "memory");
}
__device__ __forceinline__ void arrive_cluster(uint32_t a) {
    asm volatile("mbarrier.arrive.release.cluster.shared::cluster.b64 _, [%0];"
                 :: "r"(a) : "memory");
}
__device__ __forceinline__ void ybar_wait(uint32_t a, uint32_t parity) {
    asm volatile(
        "{\n\t.reg .pred P;\n\t"
        "W_%=:\n\t"
        "mbarrier.try_wait.parity.acquire.cluster.shared::cta.b64 P, [%0], %1, 0x989680;\n\t"
        "@P bra.uni D_%=;\n\t"
        "bra.uni W_%=;\n\t"
        "D_%=:\n\t}"
        :: "r"(a), "r"(parity) : "memory");
}

// ===================== SMEM layout (both kernels) =====================
#define S1_OFF    0               // smem W half (32 rows)          131072 B
#define S0_OFF    131072          // staging (16 rows)               65536 B
#define YB_OFF    196608          // ybuf[2][1024] floats             8192 B
#define P_OFF     204800          // P[6][64]                         1536 B
#define OBS_OFF   206336          // obs_s[64]                         256 B
#define RED_OFF   206592          // red_s[8]                           32 B
#define BAR_OFF   206624          // wbar0,wbar1,ybar0,ybar1            32 B
#define SMEM_BYTES 206656

__global__ __launch_bounds__(NTHREADS, 1)
void ctrnn_cluster_kernel(const float* __restrict__ obs,  const float* __restrict__ v0,
                          const float* __restrict__ tau,  const float* __restrict__ gain,
                          const float* __restrict__ bias, const float* __restrict__ W,
                          const float* __restrict__ mask, const float* __restrict__ E,
                          const float* __restrict__ D,    float* __restrict__ out)
{
    extern __shared__ char sm[];
    float4* S1f4  = (float4*)(sm + S1_OFF);
    float4* S0f4  = (float4*)(sm + S0_OFF);
    float*  YB    = (float*)(sm + YB_OFF);     // [2][1024] plain floats
    float*  P     = (float*)(sm + P_OFF);      // [6][64]
    float*  obs_s = (float*)(sm + OBS_OFF);
    float*  red_s = (float*)(sm + RED_OFF);

    const int tid  = threadIdx.x;
    const int warp = tid >> 5;
    const int lane = tid & 31;
    const int group = blockIdx.x >> 4;
    const int cig   = blockIdx.x & 15;         // == cluster ctarank
    const int base  = cig * ROWS_CTA;

    const uint32_t S0a   = (uint32_t)__cvta_generic_to_shared(S0f4);
    const uint32_t S1a   = (uint32_t)__cvta_generic_to_shared(S1f4);
    const uint32_t YBa   = (uint32_t)__cvta_generic_to_shared(YB);
    const uint32_t wbar0 = (uint32_t)__cvta_generic_to_shared(sm + BAR_OFF);
    const uint32_t wbar1 = wbar0 + 8;
    const uint32_t ybar0 = wbar0 + 16;
    const uint32_t ybar1 = wbar0 + 24;

    if (tid == 0) {
        mbar_init(wbar0, 1);
        mbar_init(wbar1, 1);
        mbar_init(ybar0, 16);   // 16 producer-CTA arrivals per phase
        mbar_init(ybar1, 16);
        asm volatile("fence.proxy.async.shared::cta;" ::: "memory");
    }
    __syncthreads();
    // all CTAs' ybar inits must be visible before any remote arrive
    asm volatile("barrier.cluster.arrive.aligned;" ::: "memory");
    asm volatile("barrier.cluster.wait.aligned;"   ::: "memory");

    if (tid == 0) {
        const char* g = (const char*)(W + ((size_t)(group * BPG) * NN + base) * NN);
        issue_chunks(S0a, g, 65536, wbar0);      // part1 of batch 0
    }

    float4 Wreg[4][8];
    int cw0 = 0, cw1 = 0;       // W-load mbar phases
    int cy0 = 0, cy1 = 0;       // y-exchange mbar phases

    for (int bi = 0; bi < BPG; bi++) {
        const int b = group * BPG + bi;
        const char* gW = (const char*)(W + ((size_t)b * NN + base) * NN);

        // ---------- W: part1 -> registers (warps 0-3) ----------
        mbar_wait(wbar0, (uint32_t)(cw0 & 1)); cw0++;
        if (warp < 4) {
            #pragma unroll
            for (int r = 0; r < 4; r++)
                #pragma unroll
                for (int j = 0; j < 8; j++)
                    Wreg[r][j] = S0f4[(warp * 4 + r) * 256 + j * 32 + lane];
        }
        __syncthreads();
        if (tid == 0) {
            issue_chunks(S0a, gW + 65536, 65536, wbar0);     // part2
            issue_chunks(S1a, gW + 131072, 131072, wbar1);   // smem half
        }

        // ---------- prologue: params + y0 push to all 16 CTAs ----------
        if (tid < NOBS) obs_s[tid] = obs[(size_t)b * NOBS + tid];
        __syncthreads();
        if (tid < ROWS_CTA) {
            const int n = base + tid;
            const size_t o = (size_t)b * NN + n;
            float vv = v0[o], gg = gain[o], bb = bias[o], mm = mask[o];
            P[0 * 64 + tid] = vv;
            P[1 * 64 + tid] = DT_F / tau[o];
            P[3 * 64 + tid] = gg;
            P[4 * 64 + tid] = bb;
            P[5 * 64 + tid] = mm;
            const float* Er = E + o * NOBS;
            float s = 0.f;
            #pragma unroll
            for (int q = 0; q < NOBS; q++) s += Er[q] * obs_s[q];
            P[2 * 64 + tid] = s;
            float y0 = tanhf(gg * (vv + bb)) * mm;
            const uint32_t la = YBa + (uint32_t)(0 * NN + n) * 4u;   // ybuf[0][n]
            #pragma unroll
            for (int k = 0; k < CPB; k++)
                st_cluster_f32(mapa_u32(la, (uint32_t)k), y0);
        }
        __syncthreads();                                   // all y0 stores issued
        if (warp == 0 && lane < CPB)
            arrive_cluster(mapa_u32(ybar0, (uint32_t)lane));

        // ---------- W: part2 -> registers (warps 4-7); smem half ready ----------
        mbar_wait(wbar0, (uint32_t)(cw0 & 1)); cw0++;
        if (warp >= 4) {
            #pragma unroll
            for (int r = 0; r < 4; r++)
                #pragma unroll
                for (int j = 0; j < 8; j++)
                    Wreg[r][j] = S0f4[((warp - 4) * 4 + r) * 256 + j * 32 + lane];
        }
        mbar_wait(wbar1, (uint32_t)(cw1 & 1)); cw1++;
        __syncthreads();                                   // S0 free
        if (tid == 0 && bi + 1 < BPG) {
            const char* gn = (const char*)(W + ((size_t)(b + 1) * NN + base) * NN);
            issue_chunks(S0a, gn, 65536, wbar0);           // next part1
        }

        // ---------- iterations ----------
        const float4* S1w = S1f4 + (size_t)(warp * 4) * 256;
        for (int t = 1; t <= NITERS; t++) {
            // wait for step t-1 data (parity (t-1)&1) in LOCAL ybuf
            if (((t - 1) & 1) == 0) { ybar_wait(ybar0, (uint32_t)(cy0 & 1)); cy0++; }
            else                     { ybar_wait(ybar1, (uint32_t)(cy1 & 1)); cy1++; }
            const float4* Y4 = (const float4*)(YB + ((t - 1) & 1) * NN);

            float ar0 = 0.f, ar1 = 0.f, ar2 = 0.f, ar3 = 0.f;
            float as0 = 0.f, as1 = 0.f, as2 = 0.f, as3 = 0.f;
            #pragma unroll
            for (int j = 0; j < 8; j++) {
                const float4 y4 = Y4[j * 32 + lane];
                float4 w;
                w = Wreg[0][j];                   ar0 += w.x*y4.x; ar0 += w.y*y4.y; ar0 += w.z*y4.z; ar0 += w.w*y4.w;
                w = Wreg[1][j];                   ar1 += w.x*y4.x; ar1 += w.y*y4.y; ar1 += w.z*y4.z; ar1 += w.w*y4.w;
                w = Wreg[2][j];                   ar2 += w.x*y4.x; ar2 += w.y*y4.y; ar2 += w.z*y4.z; ar2 += w.w*y4.w;
                w = Wreg[3][j];                   ar3 += w.x*y4.x; ar3 += w.y*y4.y; ar3 += w.z*y4.z; ar3 += w.w*y4.w;
                w = S1w[0 * 256 + j * 32 + lane]; as0 += w.x*y4.x; as0 += w.y*y4.y; as0 += w.z*y4.z; as0 += w.w*y4.w;
                w = S1w[1 * 256 + j * 32 + lane]; as1 += w.x*y4.x; as1 += w.y*y4.y; as1 += w.z*y4.z; as1 += w.w*y4.w;
                w = S1w[2 * 256 + j * 32 + lane]; as2 += w.x*y4.x; as2 += w.y*y4.y; as2 += w.z*y4.z; as2 += w.w*y4.w;
                w = S1w[3 * 256 + j * 32 + lane]; as3 += w.x*y4.x; as3 += w.y*y4.y; as3 += w.z*y4.z; as3 += w.w*y4.w;
            }
            #pragma unroll
            for (int off = 16; off > 0; off >>= 1) {
                ar0 += __shfl_xor_sync(0xffffffffu, ar0, off);
                ar1 += __shfl_xor_sync(0xffffffffu, ar1, off);
                ar2 += __shfl_xor_sync(0xffffffffu, ar2, off);
                ar3 += __shfl_xor_sync(0xffffffffu, ar3, off);
                as0 += __shfl_xor_sync(0xffffffffu, as0, off);
                as1 += __shfl_xor_sync(0xffffffffu, as1, off);
                as2 += __shfl_xor_sync(0xffffffffu, as2, off);
                as3 += __shfl_xor_sync(0xffffffffu, as3, off);
            }

            if (lane < 8) {
                float dot;
                int rloc;
                if (lane < 4) {
                    dot  = (lane == 0) ? ar0 : (lane == 1) ? ar1 : (lane == 2) ? ar2 : ar3;
                    rloc = warp * 4 + lane;
                } else {
                    dot  = (lane == 4) ? as0 : (lane == 5) ? as1 : (lane == 6) ? as2 : as3;
                    rloc = 32 + warp * 4 + (lane - 4);
                }
                float v  = P[0 * 64 + rloc];
                float nv = (v + P[1 * 64 + rloc] * (dot + P[2 * 64 + rloc] - v)) * P[5 * 64 + rloc];
                P[0 * 64 + rloc] = nv;
                float ov = (t < NITERS)
                    ? tanhf(P[3 * 64 + rloc] * (nv + P[4 * 64 + rloc])) * P[5 * 64 + rloc]
                    : nv;
                const uint32_t la = YBa + (uint32_t)((t & 1) * NN + base + rloc) * 4u;
                #pragma unroll
                for (int k = 0; k < CPB; k++)
                    st_cluster_f32(mapa_u32(la, (uint32_t)k), ov);
            }
            __syncthreads();                               // all stores issued
            if (warp == 0 && lane < CPB)
                arrive_cluster(mapa_u32((t & 1) ? ybar1 : ybar0, (uint32_t)lane));
        }

        // ---------- decode: wait final v (t=9, parity 1), each CTA one action ----------
        ybar_wait(ybar1, (uint32_t)(cy1 & 1)); cy1++;
        {
            const float* vf = YB + NN;                     // ybuf[1] holds final v
            const float* Dr = D + ((size_t)b * NACT + cig) * NN;
            float p = 0.f;
            for (int i = tid; i < NN; i += NTHREADS) p += Dr[i] * vf[i];
            #pragma unroll
            for (int off = 16; off > 0; off >>= 1)
                p += __shfl_xor_sync(0xffffffffu, p, off);
            if (lane == 0) red_s[warp] = p;
            __syncthreads();
            if (tid == 0) {
                float s = 0.f;
                #pragma unroll
                for (int j = 0; j < 8; j++) s += red_s[j];
                out[b * NACT + cig] = s;
            }
        }
        __syncthreads();                                   // P/red/obs free for next batch
    }

    // exit hygiene: no CTA leaves while peers may still push into its SMEM
    asm volatile("barrier.cluster.arrive.aligned;" ::: "memory");
    asm volatile("barrier.cluster.wait.aligned;"   ::: "memory");
}

// ===================== fallback: R8 L2 tag-exchange kernel =====================
__device__ u64 g_ybuf[2][BATCH][NN];

__global__ void ctrnn_init_kernel() {
    int i = blockIdx.x * blockDim.x + threadIdx.x;
    if (i < 2 * BATCH * NN) ((u64*)g_ybuf)[i] = 0ull;
}
__device__ __forceinline__ u64 ldcg64(const u64* p) {
    u64 v;
    asm volatile("ld.global.cg.u64 %0, [%1];" : "=l"(v) : "l"(p));
    return v;
}
__device__ __forceinline__ void stcg64(u64* p, u64 v) {
    asm volatile("st.global.cg.u64 [%0], %1;" :: "l"(p), "l"(v) : "memory");
}
__device__ __forceinline__ void settle4(const u64* src, unsigned exp, float* y_s, int tid) {
    u64 r0 = ldcg64(src + tid);
    u64 r1 = ldcg64(src + tid + 256);
    u64 r2 = ldcg64(src + tid + 512);
    u64 r3 = ldcg64(src + tid + 768);
    while ((unsigned)(r0 >> 32) != exp) { __nanosleep(20); r0 = ldcg64(src + tid); }
    while ((unsigned)(r1 >> 32) != exp) { __nanosleep(20); r1 = ldcg64(src + tid + 256); }
    while ((unsigned)(r2 >> 32) != exp) { __nanosleep(20); r2 = ldcg64(src + tid + 512); }
    while ((unsigned)(r3 >> 32) != exp) { __nanosleep(20); r3 = ldcg64(src + tid + 768); }
    y_s[tid]       = __uint_as_float((unsigned)(r0 & 0xffffffffu));
    y_s[tid + 256] = __uint_as_float((unsigned)(r1 & 0xffffffffu));
    y_s[tid + 512] = __uint_as_float((unsigned)(r2 & 0xffffffffu));
    y_s[tid + 768] = __uint_as_float((unsigned)(r3 & 0xffffffffu));
}

__global__ __launch_bounds__(NTHREADS, 1)
void ctrnn_l2_kernel(const float* __restrict__ obs,  const float* __restrict__ v0,
                     const float* __restrict__ tau,  const float* __restrict__ gain,
                     const float* __restrict__ bias, const float* __restrict__ W,
                     const float* __restrict__ mask, const float* __restrict__ E,
                     const float* __restrict__ D,    float* __restrict__ out)
{
    extern __shared__ char sm[];
    float4* S1f4  = (float4*)(sm + S1_OFF);
    float4* S0f4  = (float4*)(sm + S0_OFF);
    float*  y_s0  = (float*)(sm + YB_OFF);
    float*  y_s1  = y_s0 + NN;
    float*  P     = (float*)(sm + P_OFF);
    float*  obs_s = (float*)(sm + OBS_OFF);
    float*  red_s = (float*)(sm + RED_OFF);

    const int tid  = threadIdx.x;
    const int warp = tid >> 5;
    const int lane = tid & 31;
    const int group = blockIdx.x >> 4;
    const int cig   = blockIdx.x & 15;
    const int base  = cig * ROWS_CTA;

    const uint32_t mbar0 = (uint32_t)__cvta_generic_to_shared(sm + BAR_OFF);
    const uint32_t mbar1 = mbar0 + 8;
    const uint32_t S0a   = (uint32_t)__cvta_generic_to_shared(S0f4);
    const uint32_t S1a   = (uint32_t)__cvta_generic_to_shared(S1f4);

    if (tid == 0) {
        mbar_init(mbar0, 1);
        mbar_init(mbar1, 1);
        asm volatile("fence.proxy.async.shared::cta;" ::: "memory");
    }
    __syncthreads();
    if (tid == 0) {
        const char* g = (const char*)(W + ((size_t)(group * BPG) * NN + base) * NN);
        issue_chunks(S0a, g, 65536, mbar0);
    }

    float4 Wreg[4][8];
    int li0 = 0, li1 = 0;

    for (int bi = 0; bi < BPG; bi++) {
        const int b = group * BPG + bi;
        const char* gW = (const char*)(W + ((size_t)b * NN + base) * NN);

        mbar_wait(mbar0, (uint32_t)(li0 & 1)); li0++;
        if (warp < 4) {
            #pragma unroll
            for (int r = 0; r < 4; r++)
                #pragma unroll
                for (int j = 0; j < 8; j++)
                    Wreg[r][j] = S0f4[(warp * 4 + r) * 256 + j * 32 + lane];
        }
        __syncthreads();
        if (tid == 0) {
            issue_chunks(S0a, gW + 65536, 65536, mbar0);
            issue_chunks(S1a, gW + 131072, 131072, mbar1);
        }

        if (tid < NOBS) obs_s[tid] = obs[(size_t)b * NOBS + tid];
        __syncthreads();
        if (tid < ROWS_CTA) {
            const int n = base + tid;
            const size_t o = (size_t)b * NN + n;
            float vv = v0[o], gg = gain[o], bb = bias[o], mm = mask[o];
            P[0 * 64 + tid] = vv;
            P[1 * 64 + tid] = DT_F / tau[o];
            P[3 * 64 + tid] = gg;
            P[4 * 64 + tid] = bb;
            P[5 * 64 + tid] = mm;
            const float* Er = E + o * NOBS;
            float s = 0.f;
            #pragma unroll
            for (int q = 0; q < NOBS; q++) s += Er[q] * obs_s[q];
            P[2 * 64 + tid] = s;
            float y0 = tanhf(gg * (vv + bb)) * mm;
            stcg64(&g_ybuf[0][b][n], ((u64)1 << 32) | (u64)__float_as_uint(y0));
        }

        mbar_wait(mbar0, (uint32_t)(li0 & 1)); li0++;
        if (warp >= 4) {
            #pragma unroll
            for (int r = 0; r < 4; r++)
                #pragma unroll
                for (int j = 0; j < 8; j++)
                    Wreg[r][j] = S0f4[((warp - 4) * 4 + r) * 256 + j * 32 + lane];
        }
        mbar_wait(mbar1, (uint32_t)(li1 & 1)); li1++;
        __syncthreads();
        if (tid == 0 && bi + 1 < BPG) {
            const char* gn = (const char*)(W + ((size_t)(b + 1) * NN + base) * NN);
            issue_chunks(S0a, gn, 65536, mbar0);
        }

        const float4* S1w = S1f4 + (size_t)(warp * 4) * 256;
        for (int t = 1; t <= NITERS; t++) {
            float* ys = (t & 1) ? y_s1 : y_s0;
            settle4(&g_ybuf[(t - 1) & 1][b][0], (unsigned)t, ys, tid);
            __syncthreads();
            const float4* Y4 = (const float4*)ys;

            float ar0 = 0.f, ar1 = 0.f, ar2 = 0.f, ar3 = 0.f;
            float as0 = 0.f, as1 = 0.f, as2 = 0.f, as3 = 0.f;
            #pragma unroll
            for (int j = 0; j < 8; j++) {
                const float4 y4 = Y4[j * 32 + lane];
                float4 w;
                w = Wreg[0][j];                   ar0 += w.x*y4.x; ar0 += w.y*y4.y; ar0 += w.z*y4.z; ar0 += w.w*y4.w;
                w = Wreg[1][j];                   ar1 += w.x*y4.x; ar1 += w.y*y4.y; ar1 += w.z*y4.z; ar1 += w.w*y4.w;
                w = Wreg[2][j];                   ar2 += w.x*y4.x; ar2 += w.y*y4.y; ar2 += w.z*y4.z; ar2 += w.w*y4.w;
                w = Wreg[3][j];                   ar3 += w.x*y4.x; ar3 += w.y*y4.y; ar3 += w.z*y4.z; ar3 += w.w*y4.w;
                w = S1w[0 * 256 + j * 32 + lane]; as0 += w.x*y4.x; as0 += w.y*y4.y; as0 += w.z*y4.z; as0 += w.w*y4.w;
                w = S1w[1 * 256 + j * 32 + lane]; as1 += w.x*y4.x; as1 += w.y*y4.y; as1 += w.z*y4.z; as1 += w.w*y4.w;
                w = S1w[2 * 256 + j * 32 + lane]; as2 += w.x*y4.x; as2 += w.y*y4.y; as2 += w.z*y4.z; as2 += w.w*y4.w;
                w = S1w[3 * 256 + j * 32 + lane]; as3 += w.x*y4.x; as3 += w.y*y4.y; as3 += w.z*y4.z; as3 += w.w*y4.w;
            }
            #pragma unroll
            for (int off = 16; off > 0; off >>= 1) {
                ar0 += __shfl_xor_sync(0xffffffffu, ar0, off);
                ar1 += __shfl_xor_sync(0xffffffffu, ar1, off);
                ar2 += __shfl_xor_sync(0xffffffffu, ar2, off);
                ar3 += __shfl_xor_sync(0xffffffffu, ar3, off);
                as0 += __shfl_xor_sync(0xffffffffu, as0, off);
                as1 += __shfl_xor_sync(0xffffffffu, as1, off);
                as2 += __shfl_xor_sync(0xffffffffu, as2, off);
                as3 += __shfl_xor_sync(0xffffffffu, as3, off);
            }
            if (lane < 8) {
                float dot;
                int rloc;
                if (lane < 4) {
                    dot  = (lane == 0) ? ar0 : (lane == 1) ? ar1 : (lane == 2) ? ar2 : ar3;
                    rloc = warp * 4 + lane;
                } else {
                    dot  = (lane == 4) ? as0 : (lane == 5) ? as1 : (lane == 6) ? as2 : as3;
                    rloc = 32 + warp * 4 + (lane - 4);
                }
                float v  = P[0 * 64 + rloc];
                float nv = (v + P[1 * 64 + rloc] * (dot + P[2 * 64 + rloc] - v)) * P[5 * 64 + rloc];
                P[0 * 64 + rloc] = nv;
                float ov = (t < NITERS)
                    ? tanhf(P[3 * 64 + rloc] * (nv + P[4 * 64 + rloc])) * P[5 * 64 + rloc]
                    : nv;
                stcg64(&g_ybuf[t & 1][b][base + rloc],
                       ((u64)(unsigned)(t + 1) << 32) | (u64)__float_as_uint(ov));
            }
        }

        settle4(&g_ybuf[NITERS & 1][b][0], (unsigned)(NITERS + 1), y_s0, tid);
        __syncthreads();
        {
            const float* Dr = D + ((size_t)b * NACT + cig) * NN;
            float p = 0.f;
            for (int i = tid; i < NN; i += NTHREADS) p += Dr[i] * y_s0[i];
            #pragma unroll
            for (int off = 16; off > 0; off >>= 1)
                p += __shfl_xor_sync(0xffffffffu, p, off);
            if (lane == 0) red_s[warp] = p;
            __syncthreads();
            if (tid == 0) {
                float s = 0.f;
                #pragma unroll
                for (int j = 0; j < 8; j++) s += red_s[j];
                out[b * NACT + cig] = s;
            }
        }
        __syncthreads();
    }
}

// ===================== launcher =====================
extern "C" void kernel_launch(void* const* d_in, const int* in_sizes, int n_in,
                              void* d_out, int out_size) {
    const float* obs  = (const float*)d_in[0];
    const float* v0   = (const float*)d_in[1];
    const float* tau  = (const float*)d_in[2];
    const float* gain = (const float*)d_in[3];
    const float* bias = (const float*)d_in[4];
    const float* W    = (const float*)d_in[5];
    const float* mask = (const float*)d_in[6];
    const float* E    = (const float*)d_in[7];
    const float* D    = (const float*)d_in[8];
    float* out = (float*)d_out;

    cudaFuncSetAttribute(ctrnn_cluster_kernel,
                         cudaFuncAttributeMaxDynamicSharedMemorySize, SMEM_BYTES);
    cudaFuncSetAttribute(ctrnn_cluster_kernel,
                         cudaFuncAttributeNonPortableClusterSizeAllowed, 1);

    cudaLaunchConfig_t cfg = {};
    cfg.gridDim  = dim3(NCLUST * CPB, 1, 1);
    cfg.blockDim = dim3(NTHREADS, 1, 1);
    cfg.dynamicSmemBytes = SMEM_BYTES;
    cudaLaunchAttribute attrs[1];
    attrs[0].id = cudaLaunchAttributeClusterDimension;
    attrs[0].val.clusterDim.x = CPB;
    attrs[0].val.clusterDim.y = 1;
    attrs[0].val.clusterDim.z = 1;
    cfg.attrs = attrs;
    cfg.numAttrs = 1;

    // Gate 1: can a 16-CTA cluster be placed at all for this kernel/config?
    int potential = 0;
    cudaLaunchConfig_t pcfg = cfg;      // potential-size query ignores cluster attr
    pcfg.attrs = nullptr;
    pcfg.numAttrs = 0;
    cudaError_t perr = cudaOccupancyMaxPotentialClusterSize(
        &potential, ctrnn_cluster_kernel, &pcfg);

    // Gate 2 (advisory): co-resident cluster count, when the query works.
    int maxClusters = 0;
    cudaError_t qerr = cudaOccupancyMaxActiveClusters(&maxClusters,
                                                      ctrnn_cluster_kernel, &cfg);

    bool use_cluster = false;
    if (perr == cudaSuccess && potential >= CPB) {
        // placement possible; require co-residency confirmation only if that
        // query succeeded (inter-cluster independence keeps waves deadlock-free)
        use_cluster = (qerr != cudaSuccess) || (maxClusters >= NCLUST);
    }
    cudaGetLastError();   // clear any sticky error from the queries

    if (use_cluster) {
        cudaLaunchKernelEx(&cfg, ctrnn_cluster_kernel,
                           obs, v0, tau, gain, bias, W, mask, E, D, out);
    } else {
        // fallback: proven L2 tag-exchange path (R8, 233 us)
        cudaFuncSetAttribute(ctrnn_l2_kernel,
                             cudaFuncAttributeMaxDynamicSharedMemorySize, SMEM_BYTES);
        ctrnn_init_kernel<<<(2 * BATCH * NN + 255) / 256, 256>>>();
        ctrnn_l2_kernel<<<NCLUST * CPB, NTHREADS, SMEM_BYTES>>>(
            obs, v0, tau, gain, bias, W, mask, E, D, out);
    }
}